// round 15
// baseline (speedup 1.0000x reference)
#include <cuda_runtime.h>
#include <math.h>

#define NB 4
#define NH 480
#define NW 640
#define NSEM 16
#define NC 20
#define MM 480
#define VRD 100
#define NZV 80
#define BANDLO 13
#define BANDN 12

#define NSPLAT_BLK ((NB * NH * NW + 255) / 256)            /* 4800 */
#define NCOPY_BLK ((NB * NC * MM * (MM / 8) + 255) / 256)  /* 9000 */
#define NPROJ_BLK ((NB * VRD * VRD * 8 + 255) / 256)       /* 1250 */
#define NFIX_BLK ((NB * MM * MM + 255) / 256)              /* 3600 */

__device__ __align__(16) float g_vox0[NB][VRD][VRD][NZV];
__device__ __align__(16) float g_voxC[NB][VRD][VRD][BANDN][NSEM];
__device__ __align__(16) float g_compact2[NB][VRD * VRD][20];
__device__ float g_pose[NB][4];

__device__ __forceinline__ void red_add_v4(float* p, float a, float b, float c, float d) {
    asm volatile("red.global.add.v4.f32 [%0], {%1, %2, %3, %4};"
                 :: "l"(p), "f"(a), "f"(b), "f"(c), "f"(d) : "memory");
}
__device__ __forceinline__ void red_add_v2(float* p, float a, float b) {
    asm volatile("red.global.add.v2.f32 [%0], {%1, %2};"
                 :: "l"(p), "f"(a), "f"(b) : "memory");
}

// Shared partition predicate: explicit round-to-nearest intrinsics so every
// caller computes BIT-IDENTICAL results. True => fix owns the pixel (writes
// all 20 channels); false => copy owns it. Margin >= tap deviation 1+sqrt2.
__device__ __forceinline__ bool box_maybe(int w, int h, float ct, float sn,
                                          float tx, float ty) {
    const float step = 2.0f / 479.0f;
    float gqx = __fadd_rn(__fsub_rn(__fmul_rn((float)w, step), 1.0f), tx);
    float gqy = __fadd_rn(__fsub_rn(__fmul_rn((float)h, step), 1.0f), ty);
    float r0 = __fsub_rn(__fmul_rn(gqx, ct), __fmul_rn(gqy, sn));
    float r1 = __fadd_rn(__fmul_rn(gqx, sn), __fmul_rn(gqy, ct));
    float rx = __fmul_rn(__fmul_rn(__fadd_rn(r0, 1.0f), 0.5f), 479.0f);
    float ry = __fmul_rn(__fmul_rn(__fadd_rn(r1, 1.0f), 0.5f), 479.0f);
    return (rx >= 186.0f) && (rx <= 293.0f) && (ry >= 236.0f) && (ry <= 343.0f);
}

// ---------------------------------------------------------------------------
__global__ void zero_pose_kernel(const float* __restrict__ pose_obs,
                                 const float* __restrict__ poses_last,
                                 float* __restrict__ poses_out) {
    if (blockIdx.x == 0 && threadIdx.x < NB) {
        int b = threadIdx.x;
        const float R2D = 57.29577951308232f;
        float plx = poses_last[3 * b + 0];
        float ply = poses_last[3 * b + 1];
        float plo = poses_last[3 * b + 2];
        float dx = pose_obs[3 * b + 0];
        float dy = pose_obs[3 * b + 1];
        float dth = pose_obs[3 * b + 2];
        float r = __fdiv_rn(plo, R2D);
        float sr = sinf(r), cr = cosf(r);
        float yy = __fadd_rn(__fadd_rn(ply, __fmul_rn(dx, sr)), __fmul_rn(dy, cr));
        float xx = __fsub_rn(__fadd_rn(plx, __fmul_rn(dx, cr)), __fmul_rn(dy, sr));
        float oo = __fadd_rn(plo, __fmul_rn(dth, R2D));
        oo = __fadd_rn(fmodf(__fsub_rn(oo, 180.0f), 360.0f), 180.0f);
        oo = __fsub_rn(fmodf(__fadd_rn(oo, 180.0f), 360.0f), 180.0f);
        poses_out[3 * b + 0] = xx;
        poses_out[3 * b + 1] = yy;
        poses_out[3 * b + 2] = oo;
        float stx = __fdiv_rn(-__fsub_rn(__fdiv_rn(__fmul_rn(xx, 100.0f), 5.0f), 240.0f), 240.0f);
        float sty = __fdiv_rn(-__fsub_rn(__fdiv_rn(__fmul_rn(yy, 100.0f), 5.0f), 240.0f), 240.0f);
        float tt = __fdiv_rn(__fmul_rn(__fsub_rn(90.0f, oo), 3.14159265358979323846f), 180.0f);
        g_pose[b][0] = cosf(tt);
        g_pose[b][1] = sinf(tt);
        g_pose[b][2] = stx;
        g_pose[b][3] = sty;
    }
    const int na = NB * VRD * VRD * NZV / 4;
    const int nb = NB * VRD * VRD * BANDN * NSEM / 4;
    float4* a = reinterpret_cast<float4*>(&g_vox0[0][0][0][0]);
    float4* c = reinterpret_cast<float4*>(&g_voxC[0][0][0][0][0]);
    float4 z = make_float4(0.f, 0.f, 0.f, 0.f);
    int stride = gridDim.x * blockDim.x;
    for (int i = blockIdx.x * blockDim.x + threadIdx.x; i < na; i += stride) a[i] = z;
    for (int i = blockIdx.x * blockDim.x + threadIdx.x; i < nb; i += stride) c[i] = z;
}

// ---------------------------------------------------------------------------
__global__ void splat_kernel(const float* __restrict__ obs, float focal) {
    int idx = blockIdx.x * blockDim.x + threadIdx.x;
    if (idx >= NB * NH * NW) return;
    int w = idx % NW;
    int t = idx / NW;
    int h = t % NH;
    int b = t / NH;

    size_t obs_b = (size_t)b * NC * NH * NW;
    size_t pix = (size_t)h * NW + w;
    float depth = __ldcs(obs + obs_b + (size_t)3 * NH * NW + pix);

    float X = __fdiv_rn(__fmul_rn(__fsub_rn((float)w, 319.5f), depth), focal);
    float Z = __fdiv_rn(__fmul_rn(__fsub_rn((float)(NH - 1 - h), 239.5f), depth), focal);

    float t0 = __fdiv_rn(__fadd_rn(X, 250.0f), 5.0f);
    t0 = __fmul_rn(__fdiv_rn(__fsub_rn(t0, 50.0f), 100.0f), 2.0f);
    float pos0 = __fadd_rn(__fmul_rn(t0, 50.0f), 50.0f);
    float t1 = __fdiv_rn(depth, 5.0f);
    t1 = __fmul_rn(__fdiv_rn(__fsub_rn(t1, 50.0f), 100.0f), 2.0f);
    float pos1 = __fadd_rn(__fmul_rn(t1, 50.0f), 50.0f);
    float t2 = __fdiv_rn(__fadd_rn(Z, 88.0f), 5.0f);
    t2 = __fmul_rn(__fdiv_rn(__fsub_rn(t2, 32.0f), 80.0f), 2.0f);
    float pos2 = __fadd_rn(__fmul_rn(t2, 40.0f), 40.0f);

    float f0 = floorf(pos0), f1 = floorf(pos1), f2 = floorf(pos2);
    float wg0[2], wg1[2], wg2[2];
    int i0[2], i1[2], i2[2];
#pragma unroll
    for (int o = 0; o < 2; o++) {
        float p = f0 + (float)o;
        bool s = (p > 0.0f) && (p < 100.0f);
        wg0[o] = s ? (1.0f - fabsf(__fsub_rn(pos0, p))) : 0.0f;
        i0[o] = s ? (int)p : 0;
        p = f1 + (float)o;
        s = (p > 0.0f) && (p < 100.0f);
        wg1[o] = s ? (1.0f - fabsf(__fsub_rn(pos1, p))) : 0.0f;
        i1[o] = s ? (int)p : 0;
        p = f2 + (float)o;
        s = (p > 0.0f) && (p < 80.0f);
        wg2[o] = s ? (1.0f - fabsf(__fsub_rn(pos2, p))) : 0.0f;
        i2[o] = s ? (int)p : 0;
    }
    if ((wg0[0] == 0.f && wg0[1] == 0.f) ||
        (wg1[0] == 0.f && wg1[1] == 0.f) ||
        (wg2[0] == 0.f && wg2[1] == 0.f))
        return;

    bool band = ((wg2[0] > 0.f && i2[0] >= BANDLO && i2[0] < BANDLO + BANDN) ||
                 (wg2[1] > 0.f && i2[1] >= BANDLO && i2[1] < BANDLO + BANDN));
    float sem[NSEM];
    if (band) {
#pragma unroll
        for (int s = 0; s < NSEM; s++)
            sem[s] = __ldcs(obs + obs_b + (size_t)(4 + s) * NH * NW + pix);
    }

    bool zpair = (wg2[0] > 0.f) && (wg2[1] > 0.f);
    bool zalign = zpair && ((i2[0] & 1) == 0);

#pragma unroll
    for (int a = 0; a < 2; a++) {
        if (wg0[a] == 0.f) continue;
#pragma unroll
        for (int c = 0; c < 2; c++) {
            float wac = __fmul_rn(wg0[a], wg1[c]);
            if (wac == 0.f) continue;

            float wz0 = __fmul_rn(wac, wg2[0]);
            float wz1 = __fmul_rn(wac, wg2[1]);
            float* v0base = &g_vox0[b][i1[c]][i0[a]][0];
            if (zalign) {
                red_add_v2(v0base + i2[0], wz0, wz1);
            } else {
                if (wg2[0] > 0.f) atomicAdd(v0base + i2[0], wz0);
                if (wg2[1] > 0.f) atomicAdd(v0base + i2[1], wz1);
            }

#pragma unroll
            for (int e = 0; e < 2; e++) {
                float wt = (e == 0) ? wz0 : wz1;
                if (wt == 0.f) continue;
                int zb = i2[e] - BANDLO;
                if ((unsigned)zb < (unsigned)BANDN) {
                    float* dst = &g_voxC[b][i1[c]][i0[a]][zb][0];
#pragma unroll
                    for (int q = 0; q < 4; q++)
                        red_add_v4(dst + q * 4,
                                   __fmul_rn(sem[q * 4 + 0], wt),
                                   __fmul_rn(sem[q * 4 + 1], wt),
                                   __fmul_rn(sem[q * 4 + 2], wt),
                                   __fmul_rn(sem[q * 4 + 3], wt));
                }
            }
        }
    }
}

// ---------------------------------------------------------------------------
// Guarded copy: writes ONLY pixels where box_maybe is false (fix owns the rest).
__device__ __forceinline__ void copy_body(int idx, const float* __restrict__ maps_last,
                                          float* __restrict__ map_out) {
    const int WQ = MM / 8;
    if (idx >= NB * NC * MM * WQ) return;
    int wq = idx % WQ;
    int t = idx / WQ;
    int h = t % MM;
    t = t / MM;
    int c = t % NC;
    int b = t / NC;
    int w0 = wq * 8;

    float ct = g_pose[b][0], sn = g_pose[b][1], tx = g_pose[b][2], ty = g_pose[b][3];
    bool mb[8];
    bool anyb = false;
#pragma unroll
    for (int e = 0; e < 8; e++) {
        mb[e] = box_maybe(w0 + e, h, ct, sn, tx, ty);
        anyb = anyb || mb[e];
    }

    size_t plane = (size_t)MM * MM;
    size_t off8 = (size_t)b * NC * plane + (size_t)c * plane + (size_t)h * MM + w0;
    if (!anyb) {
        float4 m4a = __ldcs(reinterpret_cast<const float4*>(maps_last + off8));
        float4 m4b = __ldcs(reinterpret_cast<const float4*>(maps_last + off8 + 4));
        m4a.x = fmaxf(m4a.x, 0.f); m4a.y = fmaxf(m4a.y, 0.f);
        m4a.z = fmaxf(m4a.z, 0.f); m4a.w = fmaxf(m4a.w, 0.f);
        m4b.x = fmaxf(m4b.x, 0.f); m4b.y = fmaxf(m4b.y, 0.f);
        m4b.z = fmaxf(m4b.z, 0.f); m4b.w = fmaxf(m4b.w, 0.f);
        __stcs(reinterpret_cast<float4*>(map_out + off8), m4a);
        __stcs(reinterpret_cast<float4*>(map_out + off8 + 4), m4b);
        return;
    }
#pragma unroll
    for (int e = 0; e < 8; e++) {
        if (mb[e]) continue;                  // fix owns this pixel
        map_out[off8 + e] = fmaxf(maps_last[off8 + e], 0.0f);
    }
}

// ---------------------------------------------------------------------------
__global__ void proj_kernel(float* __restrict__ fp_out) {
    int tid = blockIdx.x * blockDim.x + threadIdx.x;
    int cell = tid >> 3;
    int lane = tid & 7;
    if (cell >= NB * VRD * VRD) return;
    int p0 = cell % VRD;
    int t = cell / VRD;
    int p1 = t % VRD;
    int b = t / VRD;

    const float4* v0 = reinterpret_cast<const float4*>(&g_vox0[b][p1][p0][0]);
    float s_all = 0.f, s_band = 0.f;
#pragma unroll
    for (int q0 = 0; q0 < 3; q0++) {
        int q = q0 * 8 + lane;
        if (q0 == 2 && q >= NZV / 4) break;
        float4 v = __ldcs(v0 + q);
        float r0 = rintf(v.x), r1 = rintf(v.y), r2 = rintf(v.z), r3 = rintf(v.w);
        s_all += r0 + r1 + r2 + r3;
        int z = q * 4;
        if (z + 0 >= BANDLO && z + 0 < BANDLO + BANDN) s_band += r0;
        if (z + 1 >= BANDLO && z + 1 < BANDLO + BANDN) s_band += r1;
        if (z + 2 >= BANDLO && z + 2 < BANDLO + BANDN) s_band += r2;
        if (z + 3 >= BANDLO && z + 3 < BANDLO + BANDN) s_band += r3;
    }

    float ssem[NSEM];
#pragma unroll
    for (int s = 0; s < NSEM; s++) ssem[s] = 0.f;
    const float4* vc = reinterpret_cast<const float4*>(&g_voxC[b][p1][p0][0][0]);
#pragma unroll
    for (int zb0 = 0; zb0 < 2; zb0++) {
        int zb = zb0 * 8 + lane;
        if (zb >= BANDN) break;
#pragma unroll
        for (int q = 0; q < NSEM / 4; q++) {
            float4 v = __ldcs(vc + zb * (NSEM / 4) + q);
            ssem[q * 4 + 0] += rintf(v.x);
            ssem[q * 4 + 1] += rintf(v.y);
            ssem[q * 4 + 2] += rintf(v.z);
            ssem[q * 4 + 3] += rintf(v.w);
        }
    }

#pragma unroll
    for (int off = 1; off < 8; off <<= 1) {
        s_all += __shfl_xor_sync(0xffffffffu, s_all, off);
        s_band += __shfl_xor_sync(0xffffffffu, s_band, off);
#pragma unroll
        for (int s = 0; s < NSEM; s++)
            ssem[s] += __shfl_xor_sync(0xffffffffu, ssem[s], off);
    }

    if (lane == 0) {
        int sp = p1 * VRD + p0;
        float m = fminf(fmaxf(__fdiv_rn(s_band, 1.0f), 0.f), 1.f);
        float e = fminf(fmaxf(__fdiv_rn(s_all, 1.0f), 0.f), 1.f);
        float sv[NSEM];
#pragma unroll
        for (int s = 0; s < NSEM; s++)
            sv[s] = fminf(fmaxf(__fdiv_rn(ssem[s], 5.0f), 0.f), 1.f);
        float4* row = reinterpret_cast<float4*>(&g_compact2[b][sp][0]);
        row[0] = make_float4(m, e, sv[0], sv[1]);
        row[1] = make_float4(sv[2], sv[3], sv[4], sv[5]);
        row[2] = make_float4(sv[6], sv[7], sv[8], sv[9]);
        row[3] = make_float4(sv[10], sv[11], sv[12], sv[13]);
        row[4] = make_float4(sv[14], sv[15], 0.f, 0.f);
        fp_out[(size_t)b * VRD * VRD + sp] = m;
    }
}

// ---------------------------------------------------------------------------
// Fix: owns EVERY box_maybe pixel; writes all 20 channels. Disjoint from copy.
__device__ __forceinline__ void fix_body(int idx,
                                         const float* __restrict__ maps_last,
                                         float* __restrict__ map_out) {
    if (idx >= NB * MM * MM) return;
    int w = idx % MM;
    int t = idx / MM;
    int h = t % MM;
    int b = t / MM;

    float ct = g_pose[b][0], sn = g_pose[b][1], tx = g_pose[b][2], ty = g_pose[b][3];
    if (!box_maybe(w, h, ct, sn, tx, ty)) return;   // copy owns this pixel

    const float step = 2.0f / 479.0f;
    float gx = __fsub_rn(__fmul_rn((float)w, step), 1.0f);
    float gy = __fsub_rn(__fmul_rn((float)h, step), 1.0f);
    float x = __fmul_rn(__fmul_rn(__fadd_rn(__fadd_rn(gx, tx), 1.0f), 0.5f), 479.0f);
    float y = __fmul_rn(__fmul_rn(__fadd_rn(__fadd_rn(gy, ty), 1.0f), 0.5f), 479.0f);
    float x0 = floorf(x), y0 = floorf(y);
    float wxv[2] = { __fsub_rn(__fadd_rn(x0, 1.0f), x), __fsub_rn(x, x0) };
    float wyv[2] = { __fsub_rn(__fadd_rn(y0, 1.0f), y), __fsub_rn(y, y0) };

    float acc[20];
#pragma unroll
    for (int c = 0; c < 20; c++) acc[c] = 0.f;
    const float* cb = &g_compact2[b][0][0];

#pragma unroll
    for (int i = 0; i < 2; i++) {
        float qxf = x0 + (float)i;
#pragma unroll
        for (int j = 0; j < 2; j++) {
            float qyf = y0 + (float)j;
            float wk = __fmul_rn(wxv[i], wyv[j]);
            bool v = (qxf >= 0.f) && (qxf <= 479.f) && (qyf >= 0.f) && (qyf <= 479.f) && (wk > 0.f);
            if (!v) continue;
            float gqx = __fsub_rn(__fmul_rn(qxf, step), 1.0f);
            float gqy = __fsub_rn(__fmul_rn(qyf, step), 1.0f);
            float r0 = __fsub_rn(__fmul_rn(gqx, ct), __fmul_rn(gqy, sn));
            float r1 = __fadd_rn(__fmul_rn(gqx, sn), __fmul_rn(gqy, ct));
            float rx = __fmul_rn(__fmul_rn(__fadd_rn(r0, 1.0f), 0.5f), 479.0f);
            float ry = __fmul_rn(__fmul_rn(__fadd_rn(r1, 1.0f), 0.5f), 479.0f);
            float rx0 = floorf(rx);
            float ry0 = floorf(ry);
            float wrx[2] = { __fsub_rn(__fadd_rn(rx0, 1.0f), rx), __fsub_rn(rx, rx0) };
            float wry[2] = { __fsub_rn(__fadd_rn(ry0, 1.0f), ry), __fsub_rn(ry, ry0) };
#pragma unroll
            for (int di = 0; di < 2; di++) {
#pragma unroll
                for (int dj = 0; dj < 2; dj++) {
                    float fx = rx0 + (float)di;
                    float fy = ry0 + (float)dj;
                    bool inr = (fx >= 190.f) && (fx <= 289.f) && (fy >= 240.f) && (fy <= 339.f);
                    if (!inr) continue;
                    float wgt = __fmul_rn(wk, __fmul_rn(wrx[di], wry[dj]));
                    if (wgt == 0.f) continue;
                    int off = ((int)fy - 240) * VRD + ((int)fx - 190);
                    const float4* row = reinterpret_cast<const float4*>(cb + off * 20);
#pragma unroll
                    for (int q = 0; q < 5; q++) {
                        float4 v4 = row[q];
                        acc[q * 4 + 0] += wgt * v4.x;
                        acc[q * 4 + 1] += wgt * v4.y;
                        acc[q * 4 + 2] += wgt * v4.z;
                        acc[q * 4 + 3] += wgt * v4.w;
                    }
                }
            }
        }
    }

    size_t plane = (size_t)MM * MM;
    size_t pixoff = (size_t)b * NC * plane + (size_t)h * MM + w;
#pragma unroll
    for (int oc = 0; oc < NC; oc++) {
        float a;
        if (oc < 2) a = acc[oc];
        else if (oc < 4) a = 0.0f;
        else a = acc[oc - 2];
        float m = maps_last[pixoff + (size_t)oc * plane];
        map_out[pixoff + (size_t)oc * plane] = fmaxf(fmaxf(m, 0.0f), a);
    }
}

// fix blocks front-loaded; ALL copy blocks behind. Write sets disjoint
// (box_maybe partition), so in-kernel concurrency is safe.
__global__ void fix_copy_kernel(const float* __restrict__ maps_last,
                                float* __restrict__ map_out) {
    int bid = blockIdx.x;
    if (bid < NFIX_BLK) {
        fix_body(bid * 256 + threadIdx.x, maps_last, map_out);
    } else {
        int cb = bid - NFIX_BLK;                  // copy blocks [0, 9000)
        copy_body(cb * 256 + threadIdx.x, maps_last, map_out);
    }
}

// ---------------------------------------------------------------------------
extern "C" void kernel_launch(void* const* d_in, const int* in_sizes, int n_in,
                              void* d_out, int out_size) {
    const float* obs = (const float*)d_in[0];
    const float* pose_obs = (const float*)d_in[1];
    const float* maps_last = (const float*)d_in[2];
    const float* poses_last = (const float*)d_in[3];

    float* out = (float*)d_out;
    float* fp_out = out;
    float* map_out = out + (size_t)NB * VRD * VRD;
    float* poses_out = map_out + (size_t)NB * NC * MM * MM;

    float focal = (float)((NW / 2.0) / tan((79.0 / 2.0) * M_PI / 180.0));

    zero_pose_kernel<<<1024, 256>>>(pose_obs, poses_last, poses_out);
    splat_kernel<<<NSPLAT_BLK, 256>>>(obs, focal);
    proj_kernel<<<(NB * VRD * VRD * 8 + 255) / 256, 256>>>(fp_out);
    fix_copy_kernel<<<NFIX_BLK + NCOPY_BLK, 256>>>(maps_last, map_out);
}

// round 16
// speedup vs baseline: 1.0212x; 1.0212x over previous
#include <cuda_runtime.h>
#include <math.h>

#define NB 4
#define NH 480
#define NW 640
#define NSEM 16
#define NC 20
#define MM 480
#define VRD 100
#define NZV 80
#define BANDLO 13
#define BANDN 12

#define NSPLAT_BLK ((NB * NH * NW + 255) / 256)            /* 4800 */
#define NCOPY_BLK ((NB * NC * MM * (MM / 8) + 255) / 256)  /* 9000 */

__device__ __align__(16) float g_vox0[NB][VRD][VRD][NZV];
__device__ __align__(16) float g_voxC[NB][VRD][VRD][BANDN][NSEM];
__device__ __align__(16) float g_compact2[NB][VRD * VRD][20];
__device__ float g_pose[NB][4];

__device__ __forceinline__ void red_add_v4(float* p, float a, float b, float c, float d) {
    asm volatile("red.global.add.v4.f32 [%0], {%1, %2, %3, %4};"
                 :: "l"(p), "f"(a), "f"(b), "f"(c), "f"(d) : "memory");
}
__device__ __forceinline__ void red_add_v2(float* p, float a, float b) {
    asm volatile("red.global.add.v2.f32 [%0], {%1, %2};"
                 :: "l"(p), "f"(a), "f"(b) : "memory");
}

// ---------------------------------------------------------------------------
__global__ void zero_pose_kernel(const float* __restrict__ pose_obs,
                                 const float* __restrict__ poses_last,
                                 float* __restrict__ poses_out) {
    if (blockIdx.x == 0 && threadIdx.x < NB) {
        int b = threadIdx.x;
        const float R2D = 57.29577951308232f;
        float plx = poses_last[3 * b + 0];
        float ply = poses_last[3 * b + 1];
        float plo = poses_last[3 * b + 2];
        float dx = pose_obs[3 * b + 0];
        float dy = pose_obs[3 * b + 1];
        float dth = pose_obs[3 * b + 2];
        float r = __fdiv_rn(plo, R2D);
        float sr = sinf(r), cr = cosf(r);
        float yy = __fadd_rn(__fadd_rn(ply, __fmul_rn(dx, sr)), __fmul_rn(dy, cr));
        float xx = __fsub_rn(__fadd_rn(plx, __fmul_rn(dx, cr)), __fmul_rn(dy, sr));
        float oo = __fadd_rn(plo, __fmul_rn(dth, R2D));
        oo = __fadd_rn(fmodf(__fsub_rn(oo, 180.0f), 360.0f), 180.0f);
        oo = __fsub_rn(fmodf(__fadd_rn(oo, 180.0f), 360.0f), 180.0f);
        poses_out[3 * b + 0] = xx;
        poses_out[3 * b + 1] = yy;
        poses_out[3 * b + 2] = oo;
        float stx = __fdiv_rn(-__fsub_rn(__fdiv_rn(__fmul_rn(xx, 100.0f), 5.0f), 240.0f), 240.0f);
        float sty = __fdiv_rn(-__fsub_rn(__fdiv_rn(__fmul_rn(yy, 100.0f), 5.0f), 240.0f), 240.0f);
        float tt = __fdiv_rn(__fmul_rn(__fsub_rn(90.0f, oo), 3.14159265358979323846f), 180.0f);
        g_pose[b][0] = cosf(tt);
        g_pose[b][1] = sinf(tt);
        g_pose[b][2] = stx;
        g_pose[b][3] = sty;
    }
    const int na = NB * VRD * VRD * NZV / 4;
    const int nb = NB * VRD * VRD * BANDN * NSEM / 4;
    float4* a = reinterpret_cast<float4*>(&g_vox0[0][0][0][0]);
    float4* c = reinterpret_cast<float4*>(&g_voxC[0][0][0][0][0]);
    float4 z = make_float4(0.f, 0.f, 0.f, 0.f);
    int stride = gridDim.x * blockDim.x;
    for (int i = blockIdx.x * blockDim.x + threadIdx.x; i < na; i += stride) a[i] = z;
    for (int i = blockIdx.x * blockDim.x + threadIdx.x; i < nb; i += stride) c[i] = z;
}

// ---------------------------------------------------------------------------
__device__ __forceinline__ void splat_body(int idx, const float* __restrict__ obs,
                                           float focal) {
    if (idx >= NB * NH * NW) return;
    int w = idx % NW;
    int t = idx / NW;
    int h = t % NH;
    int b = t / NH;

    size_t obs_b = (size_t)b * NC * NH * NW;
    size_t pix = (size_t)h * NW + w;
    float depth = __ldcs(obs + obs_b + (size_t)3 * NH * NW + pix);

    float X = __fdiv_rn(__fmul_rn(__fsub_rn((float)w, 319.5f), depth), focal);
    float Z = __fdiv_rn(__fmul_rn(__fsub_rn((float)(NH - 1 - h), 239.5f), depth), focal);

    float t0 = __fdiv_rn(__fadd_rn(X, 250.0f), 5.0f);
    t0 = __fmul_rn(__fdiv_rn(__fsub_rn(t0, 50.0f), 100.0f), 2.0f);
    float pos0 = __fadd_rn(__fmul_rn(t0, 50.0f), 50.0f);
    float t1 = __fdiv_rn(depth, 5.0f);
    t1 = __fmul_rn(__fdiv_rn(__fsub_rn(t1, 50.0f), 100.0f), 2.0f);
    float pos1 = __fadd_rn(__fmul_rn(t1, 50.0f), 50.0f);
    float t2 = __fdiv_rn(__fadd_rn(Z, 88.0f), 5.0f);
    t2 = __fmul_rn(__fdiv_rn(__fsub_rn(t2, 32.0f), 80.0f), 2.0f);
    float pos2 = __fadd_rn(__fmul_rn(t2, 40.0f), 40.0f);

    float f0 = floorf(pos0), f1 = floorf(pos1), f2 = floorf(pos2);
    float wg0[2], wg1[2], wg2[2];
    int i0[2], i1[2], i2[2];
#pragma unroll
    for (int o = 0; o < 2; o++) {
        float p = f0 + (float)o;
        bool s = (p > 0.0f) && (p < 100.0f);
        wg0[o] = s ? (1.0f - fabsf(__fsub_rn(pos0, p))) : 0.0f;
        i0[o] = s ? (int)p : 0;
        p = f1 + (float)o;
        s = (p > 0.0f) && (p < 100.0f);
        wg1[o] = s ? (1.0f - fabsf(__fsub_rn(pos1, p))) : 0.0f;
        i1[o] = s ? (int)p : 0;
        p = f2 + (float)o;
        s = (p > 0.0f) && (p < 80.0f);
        wg2[o] = s ? (1.0f - fabsf(__fsub_rn(pos2, p))) : 0.0f;
        i2[o] = s ? (int)p : 0;
    }
    if ((wg0[0] == 0.f && wg0[1] == 0.f) ||
        (wg1[0] == 0.f && wg1[1] == 0.f) ||
        (wg2[0] == 0.f && wg2[1] == 0.f))
        return;

    bool band = ((wg2[0] > 0.f && i2[0] >= BANDLO && i2[0] < BANDLO + BANDN) ||
                 (wg2[1] > 0.f && i2[1] >= BANDLO && i2[1] < BANDLO + BANDN));
    float sem[NSEM];
    if (band) {
#pragma unroll
        for (int s = 0; s < NSEM; s++)
            sem[s] = __ldcs(obs + obs_b + (size_t)(4 + s) * NH * NW + pix);
    }

    bool zpair = (wg2[0] > 0.f) && (wg2[1] > 0.f);
    bool zalign = zpair && ((i2[0] & 1) == 0);

#pragma unroll
    for (int a = 0; a < 2; a++) {
        if (wg0[a] == 0.f) continue;
#pragma unroll
        for (int c = 0; c < 2; c++) {
            float wac = __fmul_rn(wg0[a], wg1[c]);
            if (wac == 0.f) continue;

            float wz0 = __fmul_rn(wac, wg2[0]);
            float wz1 = __fmul_rn(wac, wg2[1]);
            float* v0base = &g_vox0[b][i1[c]][i0[a]][0];
            if (zalign) {
                red_add_v2(v0base + i2[0], wz0, wz1);
            } else {
                if (wg2[0] > 0.f) atomicAdd(v0base + i2[0], wz0);
                if (wg2[1] > 0.f) atomicAdd(v0base + i2[1], wz1);
            }

#pragma unroll
            for (int e = 0; e < 2; e++) {
                float wt = (e == 0) ? wz0 : wz1;
                if (wt == 0.f) continue;
                int zb = i2[e] - BANDLO;
                if ((unsigned)zb < (unsigned)BANDN) {
                    float* dst = &g_voxC[b][i1[c]][i0[a]][zb][0];
#pragma unroll
                    for (int q = 0; q < 4; q++)
                        red_add_v4(dst + q * 4,
                                   __fmul_rn(sem[q * 4 + 0], wt),
                                   __fmul_rn(sem[q * 4 + 1], wt),
                                   __fmul_rn(sem[q * 4 + 2], wt),
                                   __fmul_rn(sem[q * 4 + 3], wt));
                }
            }
        }
    }
}

// Copy path: map_out = max(maps_last, 0) for an 8-px strip (1 thread).
// Unguarded: runs strictly before xform_fix_kernel (separate launch).
__device__ __forceinline__ void copy_body(int idx, const float* __restrict__ maps_last,
                                          float* __restrict__ map_out) {
    const int WQ = MM / 8;
    if (idx >= NB * NC * MM * WQ) return;
    int wq = idx % WQ;
    int t = idx / WQ;
    int h = t % MM;
    t = t / MM;
    int c = t % NC;
    int b = t / NC;

    size_t plane = (size_t)MM * MM;
    size_t off8 = (size_t)b * NC * plane + (size_t)c * plane + (size_t)h * MM + wq * 8;
    float4 m4a = __ldcs(reinterpret_cast<const float4*>(maps_last + off8));
    float4 m4b = __ldcs(reinterpret_cast<const float4*>(maps_last + off8 + 4));
    m4a.x = fmaxf(m4a.x, 0.f); m4a.y = fmaxf(m4a.y, 0.f);
    m4a.z = fmaxf(m4a.z, 0.f); m4a.w = fmaxf(m4a.w, 0.f);
    m4b.x = fmaxf(m4b.x, 0.f); m4b.y = fmaxf(m4b.y, 0.f);
    m4b.z = fmaxf(m4b.z, 0.f); m4b.w = fmaxf(m4b.w, 0.f);
    __stcs(reinterpret_cast<float4*>(map_out + off8), m4a);
    __stcs(reinterpret_cast<float4*>(map_out + off8 + 4), m4b);
}

// Fused (R12-proven layout): bid -> g=bid/3, r=bid%3. r<2: splat block 2g+r
// (front-loaded, first 7200 blocks); r==2: copy block g.
__global__ void splat_copy_kernel(const float* __restrict__ obs, float focal,
                                  const float* __restrict__ maps_last,
                                  float* __restrict__ map_out) {
    int bid = blockIdx.x;
    int g = bid / 3;
    int r = bid - g * 3;
    if (r == 2) {
        copy_body(g * 256 + threadIdx.x, maps_last, map_out);
    } else {
        int sb = g * 2 + r;
        if (sb < NSPLAT_BLK)
            splat_body(sb * 256 + threadIdx.x, obs, focal);
    }
}

// ---------------------------------------------------------------------------
__global__ void proj_kernel(float* __restrict__ fp_out) {
    int tid = blockIdx.x * blockDim.x + threadIdx.x;
    int cell = tid >> 3;
    int lane = tid & 7;
    if (cell >= NB * VRD * VRD) return;
    int p0 = cell % VRD;
    int t = cell / VRD;
    int p1 = t % VRD;
    int b = t / VRD;

    const float4* v0 = reinterpret_cast<const float4*>(&g_vox0[b][p1][p0][0]);
    float s_all = 0.f, s_band = 0.f;
#pragma unroll
    for (int q0 = 0; q0 < 3; q0++) {
        int q = q0 * 8 + lane;
        if (q0 == 2 && q >= NZV / 4) break;
        float4 v = __ldcs(v0 + q);
        float r0 = rintf(v.x), r1 = rintf(v.y), r2 = rintf(v.z), r3 = rintf(v.w);
        s_all += r0 + r1 + r2 + r3;
        int z = q * 4;
        if (z + 0 >= BANDLO && z + 0 < BANDLO + BANDN) s_band += r0;
        if (z + 1 >= BANDLO && z + 1 < BANDLO + BANDN) s_band += r1;
        if (z + 2 >= BANDLO && z + 2 < BANDLO + BANDN) s_band += r2;
        if (z + 3 >= BANDLO && z + 3 < BANDLO + BANDN) s_band += r3;
    }

    float ssem[NSEM];
#pragma unroll
    for (int s = 0; s < NSEM; s++) ssem[s] = 0.f;
    const float4* vc = reinterpret_cast<const float4*>(&g_voxC[b][p1][p0][0][0]);
#pragma unroll
    for (int zb0 = 0; zb0 < 2; zb0++) {
        int zb = zb0 * 8 + lane;
        if (zb >= BANDN) break;
#pragma unroll
        for (int q = 0; q < NSEM / 4; q++) {
            float4 v = __ldcs(vc + zb * (NSEM / 4) + q);
            ssem[q * 4 + 0] += rintf(v.x);
            ssem[q * 4 + 1] += rintf(v.y);
            ssem[q * 4 + 2] += rintf(v.z);
            ssem[q * 4 + 3] += rintf(v.w);
        }
    }

#pragma unroll
    for (int off = 1; off < 8; off <<= 1) {
        s_all += __shfl_xor_sync(0xffffffffu, s_all, off);
        s_band += __shfl_xor_sync(0xffffffffu, s_band, off);
#pragma unroll
        for (int s = 0; s < NSEM; s++)
            ssem[s] += __shfl_xor_sync(0xffffffffu, ssem[s], off);
    }

    if (lane == 0) {
        int sp = p1 * VRD + p0;
        float m = fminf(fmaxf(__fdiv_rn(s_band, 1.0f), 0.f), 1.f);
        float e = fminf(fmaxf(__fdiv_rn(s_all, 1.0f), 0.f), 1.f);
        float sv[NSEM];
#pragma unroll
        for (int s = 0; s < NSEM; s++)
            sv[s] = fminf(fmaxf(__fdiv_rn(ssem[s], 5.0f), 0.f), 1.f);
        float4* row = reinterpret_cast<float4*>(&g_compact2[b][sp][0]);
        row[0] = make_float4(m, e, sv[0], sv[1]);
        row[1] = make_float4(sv[2], sv[3], sv[4], sv[5]);
        row[2] = make_float4(sv[6], sv[7], sv[8], sv[9]);
        row[3] = make_float4(sv[10], sv[11], sv[12], sv[13]);
        row[4] = make_float4(sv[14], sv[15], 0.f, 0.f);
        fp_out[(size_t)b * VRD * VRD + sp] = m;
    }
}

// ---------------------------------------------------------------------------
// Fix pass (R11 body): one thread per pixel, acc[20] accumulated directly in
// the tap loop. Launched with 64-thread blocks so the ~190-block-equivalent
// active region spreads over ~750 schedulable blocks (4x more latency hiding).
__global__ void xform_fix_kernel(const float* __restrict__ maps_last,
                                 float* __restrict__ map_out) {
    int idx = blockIdx.x * blockDim.x + threadIdx.x;
    if (idx >= NB * MM * MM) return;
    int w = idx % MM;
    int t = idx / MM;
    int h = t % MM;
    int b = t / MM;

    float ct = g_pose[b][0], sn = g_pose[b][1], tx = g_pose[b][2], ty = g_pose[b][3];
    const float step = 2.0f / 479.0f;

    {
        float gqx = (float)w * step - 1.0f + tx;
        float gqy = (float)h * step - 1.0f + ty;
        float r0 = gqx * ct - gqy * sn;
        float r1 = gqx * sn + gqy * ct;
        float rx = (r0 + 1.0f) * 0.5f * 479.0f;
        float ry = (r1 + 1.0f) * 0.5f * 479.0f;
        const float MG = 4.0f;
        bool maybe = (rx >= 190.f - MG) && (rx <= 289.f + MG) &&
                     (ry >= 240.f - MG) && (ry <= 339.f + MG);
        if (!maybe) return;   // copy value already correct
    }

    float gx = __fsub_rn(__fmul_rn((float)w, step), 1.0f);
    float gy = __fsub_rn(__fmul_rn((float)h, step), 1.0f);
    float x = __fmul_rn(__fmul_rn(__fadd_rn(__fadd_rn(gx, tx), 1.0f), 0.5f), 479.0f);
    float y = __fmul_rn(__fmul_rn(__fadd_rn(__fadd_rn(gy, ty), 1.0f), 0.5f), 479.0f);
    float x0 = floorf(x), y0 = floorf(y);
    float wxv[2] = { __fsub_rn(__fadd_rn(x0, 1.0f), x), __fsub_rn(x, x0) };
    float wyv[2] = { __fsub_rn(__fadd_rn(y0, 1.0f), y), __fsub_rn(y, y0) };

    float acc[20];
#pragma unroll
    for (int c = 0; c < 20; c++) acc[c] = 0.f;
    bool any = false;
    const float* cb = &g_compact2[b][0][0];

#pragma unroll
    for (int i = 0; i < 2; i++) {
        float qxf = x0 + (float)i;
#pragma unroll
        for (int j = 0; j < 2; j++) {
            float qyf = y0 + (float)j;
            float wk = __fmul_rn(wxv[i], wyv[j]);
            bool v = (qxf >= 0.f) && (qxf <= 479.f) && (qyf >= 0.f) && (qyf <= 479.f) && (wk > 0.f);
            if (!v) continue;
            float gqx = __fsub_rn(__fmul_rn(qxf, step), 1.0f);
            float gqy = __fsub_rn(__fmul_rn(qyf, step), 1.0f);
            float r0 = __fsub_rn(__fmul_rn(gqx, ct), __fmul_rn(gqy, sn));
            float r1 = __fadd_rn(__fmul_rn(gqx, sn), __fmul_rn(gqy, ct));
            float rx = __fmul_rn(__fmul_rn(__fadd_rn(r0, 1.0f), 0.5f), 479.0f);
            float ry = __fmul_rn(__fmul_rn(__fadd_rn(r1, 1.0f), 0.5f), 479.0f);
            float rx0 = floorf(rx);
            float ry0 = floorf(ry);
            float wrx[2] = { __fsub_rn(__fadd_rn(rx0, 1.0f), rx), __fsub_rn(rx, rx0) };
            float wry[2] = { __fsub_rn(__fadd_rn(ry0, 1.0f), ry), __fsub_rn(ry, ry0) };
#pragma unroll
            for (int di = 0; di < 2; di++) {
#pragma unroll
                for (int dj = 0; dj < 2; dj++) {
                    float fx = rx0 + (float)di;
                    float fy = ry0 + (float)dj;
                    bool inr = (fx >= 190.f) && (fx <= 289.f) && (fy >= 240.f) && (fy <= 339.f);
                    if (!inr) continue;
                    float wgt = __fmul_rn(wk, __fmul_rn(wrx[di], wry[dj]));
                    if (wgt == 0.f) continue;
                    any = true;
                    int off = ((int)fy - 240) * VRD + ((int)fx - 190);
                    const float4* row = reinterpret_cast<const float4*>(cb + off * 20);
#pragma unroll
                    for (int q = 0; q < 5; q++) {
                        float4 v4 = row[q];
                        acc[q * 4 + 0] += wgt * v4.x;
                        acc[q * 4 + 1] += wgt * v4.y;
                        acc[q * 4 + 2] += wgt * v4.z;
                        acc[q * 4 + 3] += wgt * v4.w;
                    }
                }
            }
        }
    }
    if (!any) return;

    size_t plane = (size_t)MM * MM;
    size_t pixoff = (size_t)b * NC * plane + (size_t)h * MM + w;
#pragma unroll
    for (int cc = 0; cc < 18; cc++) {
        int oc = (cc < 2) ? cc : cc + 2;
        float m = maps_last[pixoff + (size_t)oc * plane];
        map_out[pixoff + (size_t)oc * plane] = fmaxf(fmaxf(m, 0.0f), acc[cc]);
    }
}

// ---------------------------------------------------------------------------
extern "C" void kernel_launch(void* const* d_in, const int* in_sizes, int n_in,
                              void* d_out, int out_size) {
    const float* obs = (const float*)d_in[0];
    const float* pose_obs = (const float*)d_in[1];
    const float* maps_last = (const float*)d_in[2];
    const float* poses_last = (const float*)d_in[3];

    float* out = (float*)d_out;
    float* fp_out = out;
    float* map_out = out + (size_t)NB * VRD * VRD;
    float* poses_out = map_out + (size_t)NB * NC * MM * MM;

    float focal = (float)((NW / 2.0) / tan((79.0 / 2.0) * M_PI / 180.0));

    zero_pose_kernel<<<1024, 256>>>(pose_obs, poses_last, poses_out);
    int half = (NSPLAT_BLK + 1) / 2;                  // 2400
    int gmax = (half > NCOPY_BLK) ? half : NCOPY_BLK; // 9000
    splat_copy_kernel<<<gmax * 3, 256>>>(obs, focal, maps_last, map_out);
    int nproj = NB * VRD * VRD * 8;
    proj_kernel<<<(nproj + 255) / 256, 256>>>(fp_out);
    int nfix = NB * MM * MM;
    xform_fix_kernel<<<(nfix + 63) / 64, 64>>>(maps_last, map_out);
}

// round 17
// speedup vs baseline: 1.0469x; 1.0251x over previous
#include <cuda_runtime.h>
#include <math.h>

#define NB 4
#define NH 480
#define NW 640
#define NSEM 16
#define NC 20
#define MM 480
#define VRD 100
#define NZV 80
#define BANDLO 13
#define BANDN 12

#define NSPLAT_BLK ((NB * NH * NW + 255) / 256)            /* 4800 */
#define NCOPY_BLK ((NB * NC * MM * (MM / 8) + 255) / 256)  /* 9000 */
#define NPROJ_BLK ((NB * VRD * VRD * 8 + 255) / 256)       /* 1250 */
#define NWL_BLK ((NB * MM * MM) / 256)                     /* 3600 exactly */

__device__ __align__(16) float g_vox0[NB][VRD][VRD][NZV];
__device__ __align__(16) float g_voxC[NB][VRD][VRD][BANDN][NSEM];
__device__ __align__(16) float g_compact2[NB][VRD * VRD][20];
__device__ float g_pose[NB][4];
__device__ int g_wl[NB * MM * MM];
__device__ int g_wl_count;

__device__ __forceinline__ void red_add_v4(float* p, float a, float b, float c, float d) {
    asm volatile("red.global.add.v4.f32 [%0], {%1, %2, %3, %4};"
                 :: "l"(p), "f"(a), "f"(b), "f"(c), "f"(d) : "memory");
}
__device__ __forceinline__ void red_add_v2(float* p, float a, float b) {
    asm volatile("red.global.add.v2.f32 [%0], {%1, %2};"
                 :: "l"(p), "f"(a), "f"(b) : "memory");
}

// ---------------------------------------------------------------------------
__global__ void zero_pose_kernel(const float* __restrict__ pose_obs,
                                 const float* __restrict__ poses_last,
                                 float* __restrict__ poses_out) {
    if (blockIdx.x == 0 && threadIdx.x == 32) g_wl_count = 0;
    if (blockIdx.x == 0 && threadIdx.x < NB) {
        int b = threadIdx.x;
        const float R2D = 57.29577951308232f;
        float plx = poses_last[3 * b + 0];
        float ply = poses_last[3 * b + 1];
        float plo = poses_last[3 * b + 2];
        float dx = pose_obs[3 * b + 0];
        float dy = pose_obs[3 * b + 1];
        float dth = pose_obs[3 * b + 2];
        float r = __fdiv_rn(plo, R2D);
        float sr = sinf(r), cr = cosf(r);
        float yy = __fadd_rn(__fadd_rn(ply, __fmul_rn(dx, sr)), __fmul_rn(dy, cr));
        float xx = __fsub_rn(__fadd_rn(plx, __fmul_rn(dx, cr)), __fmul_rn(dy, sr));
        float oo = __fadd_rn(plo, __fmul_rn(dth, R2D));
        oo = __fadd_rn(fmodf(__fsub_rn(oo, 180.0f), 360.0f), 180.0f);
        oo = __fsub_rn(fmodf(__fadd_rn(oo, 180.0f), 360.0f), 180.0f);
        poses_out[3 * b + 0] = xx;
        poses_out[3 * b + 1] = yy;
        poses_out[3 * b + 2] = oo;
        float stx = __fdiv_rn(-__fsub_rn(__fdiv_rn(__fmul_rn(xx, 100.0f), 5.0f), 240.0f), 240.0f);
        float sty = __fdiv_rn(-__fsub_rn(__fdiv_rn(__fmul_rn(yy, 100.0f), 5.0f), 240.0f), 240.0f);
        float tt = __fdiv_rn(__fmul_rn(__fsub_rn(90.0f, oo), 3.14159265358979323846f), 180.0f);
        g_pose[b][0] = cosf(tt);
        g_pose[b][1] = sinf(tt);
        g_pose[b][2] = stx;
        g_pose[b][3] = sty;
    }
    const int na = NB * VRD * VRD * NZV / 4;
    const int nb = NB * VRD * VRD * BANDN * NSEM / 4;
    float4* a = reinterpret_cast<float4*>(&g_vox0[0][0][0][0]);
    float4* c = reinterpret_cast<float4*>(&g_voxC[0][0][0][0][0]);
    float4 z = make_float4(0.f, 0.f, 0.f, 0.f);
    int stride = gridDim.x * blockDim.x;
    for (int i = blockIdx.x * blockDim.x + threadIdx.x; i < na; i += stride) a[i] = z;
    for (int i = blockIdx.x * blockDim.x + threadIdx.x; i < nb; i += stride) c[i] = z;
}

// ---------------------------------------------------------------------------
__device__ __forceinline__ void splat_body(int idx, const float* __restrict__ obs,
                                           float focal) {
    if (idx >= NB * NH * NW) return;
    int w = idx % NW;
    int t = idx / NW;
    int h = t % NH;
    int b = t / NH;

    size_t obs_b = (size_t)b * NC * NH * NW;
    size_t pix = (size_t)h * NW + w;
    float depth = __ldcs(obs + obs_b + (size_t)3 * NH * NW + pix);

    float X = __fdiv_rn(__fmul_rn(__fsub_rn((float)w, 319.5f), depth), focal);
    float Z = __fdiv_rn(__fmul_rn(__fsub_rn((float)(NH - 1 - h), 239.5f), depth), focal);

    float t0 = __fdiv_rn(__fadd_rn(X, 250.0f), 5.0f);
    t0 = __fmul_rn(__fdiv_rn(__fsub_rn(t0, 50.0f), 100.0f), 2.0f);
    float pos0 = __fadd_rn(__fmul_rn(t0, 50.0f), 50.0f);
    float t1 = __fdiv_rn(depth, 5.0f);
    t1 = __fmul_rn(__fdiv_rn(__fsub_rn(t1, 50.0f), 100.0f), 2.0f);
    float pos1 = __fadd_rn(__fmul_rn(t1, 50.0f), 50.0f);
    float t2 = __fdiv_rn(__fadd_rn(Z, 88.0f), 5.0f);
    t2 = __fmul_rn(__fdiv_rn(__fsub_rn(t2, 32.0f), 80.0f), 2.0f);
    float pos2 = __fadd_rn(__fmul_rn(t2, 40.0f), 40.0f);

    float f0 = floorf(pos0), f1 = floorf(pos1), f2 = floorf(pos2);
    float wg0[2], wg1[2], wg2[2];
    int i0[2], i1[2], i2[2];
#pragma unroll
    for (int o = 0; o < 2; o++) {
        float p = f0 + (float)o;
        bool s = (p > 0.0f) && (p < 100.0f);
        wg0[o] = s ? (1.0f - fabsf(__fsub_rn(pos0, p))) : 0.0f;
        i0[o] = s ? (int)p : 0;
        p = f1 + (float)o;
        s = (p > 0.0f) && (p < 100.0f);
        wg1[o] = s ? (1.0f - fabsf(__fsub_rn(pos1, p))) : 0.0f;
        i1[o] = s ? (int)p : 0;
        p = f2 + (float)o;
        s = (p > 0.0f) && (p < 80.0f);
        wg2[o] = s ? (1.0f - fabsf(__fsub_rn(pos2, p))) : 0.0f;
        i2[o] = s ? (int)p : 0;
    }
    if ((wg0[0] == 0.f && wg0[1] == 0.f) ||
        (wg1[0] == 0.f && wg1[1] == 0.f) ||
        (wg2[0] == 0.f && wg2[1] == 0.f))
        return;

    bool band = ((wg2[0] > 0.f && i2[0] >= BANDLO && i2[0] < BANDLO + BANDN) ||
                 (wg2[1] > 0.f && i2[1] >= BANDLO && i2[1] < BANDLO + BANDN));
    float sem[NSEM];
    if (band) {
#pragma unroll
        for (int s = 0; s < NSEM; s++)
            sem[s] = __ldcs(obs + obs_b + (size_t)(4 + s) * NH * NW + pix);
    }

    bool zpair = (wg2[0] > 0.f) && (wg2[1] > 0.f);
    bool zalign = zpair && ((i2[0] & 1) == 0);

#pragma unroll
    for (int a = 0; a < 2; a++) {
        if (wg0[a] == 0.f) continue;
#pragma unroll
        for (int c = 0; c < 2; c++) {
            float wac = __fmul_rn(wg0[a], wg1[c]);
            if (wac == 0.f) continue;

            float wz0 = __fmul_rn(wac, wg2[0]);
            float wz1 = __fmul_rn(wac, wg2[1]);
            float* v0base = &g_vox0[b][i1[c]][i0[a]][0];
            if (zalign) {
                red_add_v2(v0base + i2[0], wz0, wz1);
            } else {
                if (wg2[0] > 0.f) atomicAdd(v0base + i2[0], wz0);
                if (wg2[1] > 0.f) atomicAdd(v0base + i2[1], wz1);
            }

#pragma unroll
            for (int e = 0; e < 2; e++) {
                float wt = (e == 0) ? wz0 : wz1;
                if (wt == 0.f) continue;
                int zb = i2[e] - BANDLO;
                if ((unsigned)zb < (unsigned)BANDN) {
                    float* dst = &g_voxC[b][i1[c]][i0[a]][zb][0];
#pragma unroll
                    for (int q = 0; q < 4; q++)
                        red_add_v4(dst + q * 4,
                                   __fmul_rn(sem[q * 4 + 0], wt),
                                   __fmul_rn(sem[q * 4 + 1], wt),
                                   __fmul_rn(sem[q * 4 + 2], wt),
                                   __fmul_rn(sem[q * 4 + 3], wt));
                }
            }
        }
    }
}

// Copy: map_out = max(maps_last, 0), ALL pixels (fix overwrites its region
// later in a separate, strictly-ordered launch).
__device__ __forceinline__ void copy_body(int idx, const float* __restrict__ maps_last,
                                          float* __restrict__ map_out) {
    const int WQ = MM / 8;
    if (idx >= NB * NC * MM * WQ) return;
    int wq = idx % WQ;
    int t = idx / WQ;
    int h = t % MM;
    t = t / MM;
    int c = t % NC;
    int b = t / NC;

    size_t plane = (size_t)MM * MM;
    size_t off8 = (size_t)b * NC * plane + (size_t)c * plane + (size_t)h * MM + wq * 8;
    float4 m4a = __ldcs(reinterpret_cast<const float4*>(maps_last + off8));
    float4 m4b = __ldcs(reinterpret_cast<const float4*>(maps_last + off8 + 4));
    m4a.x = fmaxf(m4a.x, 0.f); m4a.y = fmaxf(m4a.y, 0.f);
    m4a.z = fmaxf(m4a.z, 0.f); m4a.w = fmaxf(m4a.w, 0.f);
    m4b.x = fmaxf(m4b.x, 0.f); m4b.y = fmaxf(m4b.y, 0.f);
    m4b.z = fmaxf(m4b.z, 0.f); m4b.w = fmaxf(m4b.w, 0.f);
    __stcs(reinterpret_cast<float4*>(map_out + off8), m4a);
    __stcs(reinterpret_cast<float4*>(map_out + off8 + 4), m4b);
}

// Fused (R12-proven layout): r<2: splat block 2g+r; r==2: copy block g.
__global__ void splat_copy_kernel(const float* __restrict__ obs, float focal,
                                  const float* __restrict__ maps_last,
                                  float* __restrict__ map_out) {
    int bid = blockIdx.x;
    int g = bid / 3;
    int r = bid - g * 3;
    if (r == 2) {
        copy_body(g * 256 + threadIdx.x, maps_last, map_out);
    } else {
        int sb = g * 2 + r;
        if (sb < NSPLAT_BLK)
            splat_body(sb * 256 + threadIdx.x, obs, focal);
    }
}

// ---------------------------------------------------------------------------
__device__ __forceinline__ void proj_body(int tid, float* __restrict__ fp_out) {
    int cell = tid >> 3;
    int lane = tid & 7;
    if (cell >= NB * VRD * VRD) return;
    int p0 = cell % VRD;
    int t = cell / VRD;
    int p1 = t % VRD;
    int b = t / VRD;

    const float4* v0 = reinterpret_cast<const float4*>(&g_vox0[b][p1][p0][0]);
    float s_all = 0.f, s_band = 0.f;
#pragma unroll
    for (int q0 = 0; q0 < 3; q0++) {
        int q = q0 * 8 + lane;
        if (q0 == 2 && q >= NZV / 4) break;
        float4 v = __ldcs(v0 + q);
        float r0 = rintf(v.x), r1 = rintf(v.y), r2 = rintf(v.z), r3 = rintf(v.w);
        s_all += r0 + r1 + r2 + r3;
        int z = q * 4;
        if (z + 0 >= BANDLO && z + 0 < BANDLO + BANDN) s_band += r0;
        if (z + 1 >= BANDLO && z + 1 < BANDLO + BANDN) s_band += r1;
        if (z + 2 >= BANDLO && z + 2 < BANDLO + BANDN) s_band += r2;
        if (z + 3 >= BANDLO && z + 3 < BANDLO + BANDN) s_band += r3;
    }

    float ssem[NSEM];
#pragma unroll
    for (int s = 0; s < NSEM; s++) ssem[s] = 0.f;
    const float4* vc = reinterpret_cast<const float4*>(&g_voxC[b][p1][p0][0][0]);
#pragma unroll
    for (int zb0 = 0; zb0 < 2; zb0++) {
        int zb = zb0 * 8 + lane;
        if (zb >= BANDN) break;
#pragma unroll
        for (int q = 0; q < NSEM / 4; q++) {
            float4 v = __ldcs(vc + zb * (NSEM / 4) + q);
            ssem[q * 4 + 0] += rintf(v.x);
            ssem[q * 4 + 1] += rintf(v.y);
            ssem[q * 4 + 2] += rintf(v.z);
            ssem[q * 4 + 3] += rintf(v.w);
        }
    }

#pragma unroll
    for (int off = 1; off < 8; off <<= 1) {
        s_all += __shfl_xor_sync(0xffffffffu, s_all, off);
        s_band += __shfl_xor_sync(0xffffffffu, s_band, off);
#pragma unroll
        for (int s = 0; s < NSEM; s++)
            ssem[s] += __shfl_xor_sync(0xffffffffu, ssem[s], off);
    }

    if (lane == 0) {
        int sp = p1 * VRD + p0;
        float m = fminf(fmaxf(__fdiv_rn(s_band, 1.0f), 0.f), 1.f);
        float e = fminf(fmaxf(__fdiv_rn(s_all, 1.0f), 0.f), 1.f);
        float sv[NSEM];
#pragma unroll
        for (int s = 0; s < NSEM; s++)
            sv[s] = fminf(fmaxf(__fdiv_rn(ssem[s], 5.0f), 0.f), 1.f);
        float4* row = reinterpret_cast<float4*>(&g_compact2[b][sp][0]);
        row[0] = make_float4(m, e, sv[0], sv[1]);
        row[1] = make_float4(sv[2], sv[3], sv[4], sv[5]);
        row[2] = make_float4(sv[6], sv[7], sv[8], sv[9]);
        row[3] = make_float4(sv[10], sv[11], sv[12], sv[13]);
        row[4] = make_float4(sv[14], sv[15], 0.f, 0.f);
        fp_out[(size_t)b * VRD * VRD + sp] = m;
    }
}

// Worklist build: one thread per pixel, warp-ballot compaction.
__device__ __forceinline__ void wl_body(int idx) {
    // idx < NB*MM*MM guaranteed (grid sized exactly)
    int w = idx % MM;
    int t = idx / MM;
    int h = t % MM;
    int b = t / MM;
    float ct = g_pose[b][0], sn = g_pose[b][1], tx = g_pose[b][2], ty = g_pose[b][3];
    const float step = 2.0f / 479.0f;
    float gqx = (float)w * step - 1.0f + tx;
    float gqy = (float)h * step - 1.0f + ty;
    float r0 = gqx * ct - gqy * sn;
    float r1 = gqx * sn + gqy * ct;
    float rx = (r0 + 1.0f) * 0.5f * 479.0f;
    float ry = (r1 + 1.0f) * 0.5f * 479.0f;
    const float MG = 4.0f;
    bool active = (rx >= 190.f - MG) && (rx <= 289.f + MG) &&
                  (ry >= 240.f - MG) && (ry <= 339.f + MG);
    unsigned mask = __ballot_sync(0xffffffffu, active);
    if (mask == 0) return;
    int lane = threadIdx.x & 31;
    int leader = __ffs(mask) - 1;
    int base = 0;
    if (lane == leader) base = atomicAdd(&g_wl_count, __popc(mask));
    base = __shfl_sync(0xffffffffu, base, leader);
    if (active) {
        int rank = __popc(mask & ((1u << lane) - 1u));
        g_wl[base + rank] = idx;
    }
}

// proj blocks [0, NPROJ_BLK); worklist blocks behind (independent work).
__global__ void proj_wl_kernel(float* __restrict__ fp_out) {
    int bid = blockIdx.x;
    if (bid < NPROJ_BLK) {
        proj_body(bid * 256 + threadIdx.x, fp_out);
    } else {
        wl_body((bid - NPROJ_BLK) * 256 + threadIdx.x);
    }
}

// ---------------------------------------------------------------------------
// Warp-per-pixel fix. Lane l<16 owns tap l; 5 float4 gathers per lane in
// parallel; butterfly-reduce acc[20]; lanes 0-17 write the 18 channels.
__global__ void xform_fix_kernel(const float* __restrict__ maps_last,
                                 float* __restrict__ map_out) {
    int gw = (blockIdx.x * blockDim.x + threadIdx.x) >> 5;
    int lane = threadIdx.x & 31;
    int nw = (gridDim.x * blockDim.x) >> 5;
    int count = g_wl_count;
    const float step = 2.0f / 479.0f;
    size_t plane = (size_t)MM * MM;

    for (int e = gw; e < count; e += nw) {
        int idx = g_wl[e];
        int w = idx % MM;
        int t = idx / MM;
        int h = t % MM;
        int b = t / MM;

        float ct = g_pose[b][0], sn = g_pose[b][1], tx = g_pose[b][2], ty = g_pose[b][3];

        float gx = __fsub_rn(__fmul_rn((float)w, step), 1.0f);
        float gy = __fsub_rn(__fmul_rn((float)h, step), 1.0f);
        float x = __fmul_rn(__fmul_rn(__fadd_rn(__fadd_rn(gx, tx), 1.0f), 0.5f), 479.0f);
        float y = __fmul_rn(__fmul_rn(__fadd_rn(__fadd_rn(gy, ty), 1.0f), 0.5f), 479.0f);
        float x0 = floorf(x), y0 = floorf(y);
        float wx0 = __fsub_rn(__fadd_rn(x0, 1.0f), x), wx1 = __fsub_rn(x, x0);
        float wy0 = __fsub_rn(__fadd_rn(y0, 1.0f), y), wy1 = __fsub_rn(y, y0);

        float wgt = 0.f;
        int off = 0;
        if (lane < 16) {
            int i = (lane >> 3) & 1, j = (lane >> 2) & 1;
            int di = (lane >> 1) & 1, dj = lane & 1;
            float qxf = x0 + (float)i;
            float qyf = y0 + (float)j;
            float wk = __fmul_rn(i ? wx1 : wx0, j ? wy1 : wy0);
            bool v = (qxf >= 0.f) && (qxf <= 479.f) && (qyf >= 0.f) && (qyf <= 479.f) && (wk > 0.f);
            if (v) {
                float gqx = __fsub_rn(__fmul_rn(qxf, step), 1.0f);
                float gqy = __fsub_rn(__fmul_rn(qyf, step), 1.0f);
                float r0 = __fsub_rn(__fmul_rn(gqx, ct), __fmul_rn(gqy, sn));
                float r1 = __fadd_rn(__fmul_rn(gqx, sn), __fmul_rn(gqy, ct));
                float rx = __fmul_rn(__fmul_rn(__fadd_rn(r0, 1.0f), 0.5f), 479.0f);
                float ry = __fmul_rn(__fmul_rn(__fadd_rn(r1, 1.0f), 0.5f), 479.0f);
                float rx0 = floorf(rx);
                float ry0 = floorf(ry);
                float wrx = di ? __fsub_rn(rx, rx0) : __fsub_rn(__fadd_rn(rx0, 1.0f), rx);
                float wry = dj ? __fsub_rn(ry, ry0) : __fsub_rn(__fadd_rn(ry0, 1.0f), ry);
                float fx = rx0 + (float)di;
                float fy = ry0 + (float)dj;
                bool inr = (fx >= 190.f) && (fx <= 289.f) && (fy >= 240.f) && (fy <= 339.f);
                if (inr) {
                    float wg = __fmul_rn(wk, __fmul_rn(wrx, wry));
                    if (wg != 0.f) {
                        wgt = wg;
                        off = ((int)fy - 240) * VRD + ((int)fx - 190);
                    }
                }
            }
        }

        float acc[20];
#pragma unroll
        for (int c = 0; c < 20; c++) acc[c] = 0.f;
        if (wgt != 0.f) {
            const float4* row = reinterpret_cast<const float4*>(&g_compact2[b][off][0]);
#pragma unroll
            for (int q = 0; q < 5; q++) {
                float4 v4 = row[q];
                acc[q * 4 + 0] = wgt * v4.x;
                acc[q * 4 + 1] = wgt * v4.y;
                acc[q * 4 + 2] = wgt * v4.z;
                acc[q * 4 + 3] = wgt * v4.w;
            }
        }
        // butterfly reduce across the warp (lanes >=16 contribute zeros)
#pragma unroll
        for (int s = 16; s >= 1; s >>= 1) {
#pragma unroll
            for (int c = 0; c < 18; c++)
                acc[c] += __shfl_xor_sync(0xffffffffu, acc[c], s);
        }

        if (lane < 18) {
            float a = 0.f;
#pragma unroll
            for (int c = 0; c < 18; c++) a = (lane == c) ? acc[c] : a;
            int oc = (lane < 2) ? lane : lane + 2;
            size_t po = (size_t)b * NC * plane + (size_t)oc * plane + (size_t)h * MM + w;
            float m = maps_last[po];
            map_out[po] = fmaxf(fmaxf(m, 0.0f), a);
        }
    }
}

// ---------------------------------------------------------------------------
extern "C" void kernel_launch(void* const* d_in, const int* in_sizes, int n_in,
                              void* d_out, int out_size) {
    const float* obs = (const float*)d_in[0];
    const float* pose_obs = (const float*)d_in[1];
    const float* maps_last = (const float*)d_in[2];
    const float* poses_last = (const float*)d_in[3];

    float* out = (float*)d_out;
    float* fp_out = out;
    float* map_out = out + (size_t)NB * VRD * VRD;
    float* poses_out = map_out + (size_t)NB * NC * MM * MM;

    float focal = (float)((NW / 2.0) / tan((79.0 / 2.0) * M_PI / 180.0));

    zero_pose_kernel<<<1024, 256>>>(pose_obs, poses_last, poses_out);
    int half = (NSPLAT_BLK + 1) / 2;                  // 2400
    int gmax = (half > NCOPY_BLK) ? half : NCOPY_BLK; // 9000
    splat_copy_kernel<<<gmax * 3, 256>>>(obs, focal, maps_last, map_out);
    proj_wl_kernel<<<NPROJ_BLK + NWL_BLK, 256>>>(fp_out);
    xform_fix_kernel<<<1184, 256>>>(maps_last, map_out);
}